// round 16
// baseline (speedup 1.0000x reference)
#include <cuda_runtime.h>
#include <cuda_fp16.h>
#include <math.h>

#define NC 128          // hidden / input dim
#define N_MAX 50000
#define E_MAX 800000
#define NG 64
#define SA_LD 136       // padded smem stride in halves
#define SCAN_EPT 16
#define SCAN_CHUNK (256 * SCAN_EPT)

// ---- scratch (static device globals; zero-initialized at module load) ----
__device__ __half g_h16[(size_t)N_MAX * NC];   // h (gemm output, gather payload)
__device__ __half g_x16[(size_t)N_MAX * NC];   // layer-2 gemm input (fp16)
__device__ __half g_w16a[NC * NC];             // W_src1 fp16
__device__ __half g_w16b[NC * NC];             // W_src2 fp16
__device__ float g_agg[(size_t)N_MAX * NC];
__device__ float g_asrc[N_MAX];
__device__ float g_adst[N_MAX];
__device__ float g_wdst1[NC];
__device__ float g_wdst2[NC];
__device__ int g_src[E_MAX];
__device__ int g_dst[E_MAX];
__device__ int g_batch[N_MAX];
__device__ int g_deg[N_MAX];                   // INVARIANT: zero at kernel_launch entry
__device__ int g_rowstart[N_MAX + 1];          // +1: sentinel for cnt diffs
__device__ int g_cursor[N_MAX];
__device__ int g_csr[E_MAX];
__device__ int g_tsum[(N_MAX + SCAN_CHUNK - 1) / SCAN_CHUNK * 256 + 256];

// K1: role-split fused prep+convert+hist.
//   blocks [0, EB):        edge convert + dst histogram + batch convert
//   blocks [EB, EB+16):    W_src1/2 -> fp16
//   block  EB+16:          wdst1/wdst2 folds
__global__ void __launch_bounds__(256) prep_conv(
        const float* __restrict__ Ws1, const float* __restrict__ Ws2,
        const float* __restrict__ Wd1, const float* __restrict__ ad1,
        const float* __restrict__ Wd2, const float* __restrict__ ad2,
        const void* __restrict__ ei, const void* __restrict__ batch,
        int E, int n, int EB) {
    int tid = threadIdx.x, b = blockIdx.x;

    if (b < EB) {
        // per-block int64 detection (reads first 256 edges' high words)
        __shared__ int s_or;
        if (tid == 0) s_or = 0;
        __syncthreads();
        {
            const int* w = (const int*)ei;
            int acc = w[2 * tid + 1];
            #pragma unroll
            for (int o = 16; o > 0; o >>= 1) acc |= __shfl_xor_sync(0xffffffffu, acc, o);
            if ((tid & 31) == 0) atomicOr(&s_or, acc);
        }
        __syncthreads();
        int is64 = (s_or == 0) ? 1 : 0;

        int i = b * 256 + tid;
        if (i < E) {
            int s, d;
            if (is64) {
                s = (int)((const long long*)ei)[i];
                d = (int)((const long long*)ei)[E + i];
            } else {
                s = ((const int*)ei)[i];
                d = ((const int*)ei)[E + i];
            }
            g_src[i] = s;
            g_dst[i] = d;
            atomicAdd(&g_deg[d], 1);     // deg zero on entry (invariant)
        }
        if (i < n)
            g_batch[i] = is64 ? (int)((const long long*)batch)[i] : ((const int*)batch)[i];
        return;
    }

    if (b < EB + 16) {
        int i = (b - EB) * 256 + tid;    // 16 blocks x 256 = 4096 float4s
        const float4* W14 = (const float4*)Ws1;
        const float4* W24 = (const float4*)Ws2;
        float4 v = W14[i];
        union { __half2 h[2]; uint2 u; } cv;
        cv.h[0] = __floats2half2_rn(v.x, v.y);
        cv.h[1] = __floats2half2_rn(v.z, v.w);
        ((uint2*)g_w16a)[i] = cv.u;
        v = W24[i];
        cv.h[0] = __floats2half2_rn(v.x, v.y);
        cv.h[1] = __floats2half2_rn(v.z, v.w);
        ((uint2*)g_w16b)[i] = cv.u;
        return;
    }

    // folds block
    if (tid < NC) {
        float s = 0.f;
        #pragma unroll 4
        for (int c = 0; c < NC; c++) s += Wd1[tid * NC + c] * ad1[c];
        g_wdst1[tid] = s;
    } else {
        int k = tid - NC;
        float s = 0.f;
        #pragma unroll 4
        for (int c = 0; c < NC; c++) s += Wd2[k * NC + c] * ad2[c];
        g_wdst2[k] = s;
    }
}

// K2a/b/c: discrete 3-phase exclusive scan of degrees.
__global__ void scan_phase1(int n) {
    int tid = blockIdx.x * blockDim.x + threadIdx.x;
    int base = tid * SCAN_EPT;
    int s = 0;
    #pragma unroll
    for (int i = 0; i < SCAN_EPT; i++) {
        int idx = base + i;
        if (idx < n) s += g_deg[idx];
    }
    g_tsum[tid] = s;
}

__global__ void scan_phase2(int total) {
    __shared__ int sS[1024];
    int t = threadIdx.x;
    int per = (total + 1023) / 1024;
    int lo = t * per;
    int hi = lo + per; if (hi > total) hi = total;
    int s = 0;
    for (int i = lo; i < hi; i++) s += g_tsum[i];
    sS[t] = s;
    __syncthreads();
    for (int off = 1; off < 1024; off <<= 1) {
        int v = (t >= off) ? sS[t - off] : 0;
        __syncthreads();
        sS[t] += v;
        __syncthreads();
    }
    int base = (t == 0) ? 0 : sS[t - 1];
    for (int i = lo; i < hi; i++) {
        int v = g_tsum[i];
        g_tsum[i] = base;
        base += v;
    }
}

__global__ void scan_phase3(int n) {
    int tid = blockIdx.x * blockDim.x + threadIdx.x;
    int base = g_tsum[tid];
    int start = tid * SCAN_EPT;
    #pragma unroll
    for (int i = 0; i < SCAN_EPT; i++) {
        int idx = start + i;
        if (idx < n) {
            g_rowstart[idx] = base;
            g_cursor[idx]   = base;
            base += g_deg[idx];
            if (idx == n - 1) g_rowstart[n] = base;   // sentinel
        }
    }
}

// K3: scatter SRC ids into CSR; re-zero deg for the NEXT launch/replay.
__global__ void fill_kernel(int E, int n) {
    int e = blockIdx.x * blockDim.x + threadIdx.x;
    if (e < E) {
        int slot = atomicAdd(&g_cursor[g_dst[e]], 1);
        g_csr[slot] = g_src[e];
    }
    if (e < n) g_deg[e] = 0;     // deg last read by scan_phase3; safe
}

// K4/K6: HMMA node GEMM. CTA = 128 rows x 128 cols x K=128, 8 warps. (R15 verbatim)
__global__ void __launch_bounds__(256) hmma_gemm(const float* __restrict__ x,
                                                 const float* __restrict__ att,
                                                 int layer, int n) {
    extern __shared__ __half smem[];
    __half* sA = smem;                        // 128 x SA_LD
    __half* sB = smem + 128 * SA_LD;          // 128 x SA_LD (W: [k][n])
    __shared__ __align__(16) float sAtt[NC];
    __shared__ __align__(16) float sW[NC];

    int t = threadIdx.x;
    int row0 = blockIdx.x * 128;
    const __half* W16 = (layer == 0) ? g_w16a : g_w16b;
    const float* wdst = (layer == 0) ? g_wdst1 : g_wdst2;
    if (t < NC) sAtt[t] = att[t];
    else        sW[t - NC] = wdst[t - NC];

    const float4* X4 = (const float4*)x;
    #pragma unroll
    for (int i = 0; i < 8; i++) {
        int j = i * 256 + t;
        int r = j >> 4, c8 = j & 15;
        int gr = row0 + r;
        uint4 v = make_uint4(0u, 0u, 0u, 0u);
        if (gr < n) {
            if (layer == 0) {
                float4 v0 = X4[(size_t)gr * 32 + c8 * 2];
                float4 v1 = X4[(size_t)gr * 32 + c8 * 2 + 1];
                union { __half2 h[4]; uint4 u; } cv;
                cv.h[0] = __floats2half2_rn(v0.x, v0.y);
                cv.h[1] = __floats2half2_rn(v0.z, v0.w);
                cv.h[2] = __floats2half2_rn(v1.x, v1.y);
                cv.h[3] = __floats2half2_rn(v1.z, v1.w);
                v = cv.u;
            } else {
                v = *(const uint4*)&g_x16[(size_t)gr * NC + c8 * 8];
            }
        }
        *(uint4*)&sA[r * SA_LD + c8 * 8] = v;
        uint4 wv = *(const uint4*)&W16[r * NC + c8 * 8];
        *(uint4*)&sB[r * SA_LD + c8 * 8] = wv;
    }
    __syncthreads();

    int warp = t >> 5, lane = t & 31;
    int rbase = warp * 16;

    float acc[16][4];
    #pragma unroll
    for (int j = 0; j < 16; j++)
        { acc[j][0] = 0.f; acc[j][1] = 0.f; acc[j][2] = 0.f; acc[j][3] = 0.f; }

    int a_row = rbase + (lane & 7) + ((lane >> 3) & 1) * 8;
    int a_colsel = ((lane >> 4) & 1) * 8;
    int mi = lane >> 3;
    int b_krow = (mi & 1) * 8 + (lane & 7);
    int b_ncol = (mi >> 1) * 8;

    #pragma unroll
    for (int kk = 0; kk < 8; kk++) {
        unsigned a0, a1, a2, a3;
        {
            unsigned aaddr = (unsigned)__cvta_generic_to_shared(
                &sA[a_row * SA_LD + kk * 16 + a_colsel]);
            asm volatile("ldmatrix.sync.aligned.m8n8.x4.shared.b16 {%0,%1,%2,%3}, [%4];"
                         : "=r"(a0), "=r"(a1), "=r"(a2), "=r"(a3) : "r"(aaddr));
        }
        #pragma unroll
        for (int j2 = 0; j2 < 8; j2++) {
            unsigned b0, b1, b2, b3;
            unsigned baddr = (unsigned)__cvta_generic_to_shared(
                &sB[(kk * 16 + b_krow) * SA_LD + j2 * 16 + b_ncol]);
            asm volatile("ldmatrix.sync.aligned.m8n8.x4.trans.shared.b16 {%0,%1,%2,%3}, [%4];"
                         : "=r"(b0), "=r"(b1), "=r"(b2), "=r"(b3) : "r"(baddr));
            int j = j2 * 2;
            asm volatile(
                "mma.sync.aligned.m16n8k16.row.col.f32.f16.f16.f32 "
                "{%0,%1,%2,%3}, {%4,%5,%6,%7}, {%8,%9}, {%0,%1,%2,%3};"
                : "+f"(acc[j][0]), "+f"(acc[j][1]), "+f"(acc[j][2]), "+f"(acc[j][3])
                : "r"(a0), "r"(a1), "r"(a2), "r"(a3), "r"(b0), "r"(b1));
            asm volatile(
                "mma.sync.aligned.m16n8k16.row.col.f32.f16.f16.f32 "
                "{%0,%1,%2,%3}, {%4,%5,%6,%7}, {%8,%9}, {%0,%1,%2,%3};"
                : "+f"(acc[j + 1][0]), "+f"(acc[j + 1][1]), "+f"(acc[j + 1][2]), "+f"(acc[j + 1][3])
                : "r"(a0), "r"(a1), "r"(a2), "r"(a3), "r"(b2), "r"(b3));
        }
    }

    int rL = row0 + rbase + (lane >> 2);
    int rH = rL + 8;
    int colq = (lane & 3) * 2;
    float paL = 0.f, paH = 0.f;
    #pragma unroll
    for (int j = 0; j < 16; j++) {
        float2 av = *(const float2*)&sAtt[j * 8 + colq];
        paL += acc[j][0] * av.x + acc[j][1] * av.y;
        paH += acc[j][2] * av.x + acc[j][3] * av.y;
        if (rL < n)
            *(__half2*)&g_h16[(size_t)rL * NC + j * 8 + colq] =
                __floats2half2_rn(acc[j][0], acc[j][1]);
        if (rH < n)
            *(__half2*)&g_h16[(size_t)rH * NC + j * 8 + colq] =
                __floats2half2_rn(acc[j][2], acc[j][3]);
    }
    paL += __shfl_xor_sync(0xffffffffu, paL, 1);
    paL += __shfl_xor_sync(0xffffffffu, paL, 2);
    paH += __shfl_xor_sync(0xffffffffu, paH, 1);
    paH += __shfl_xor_sync(0xffffffffu, paH, 2);
    if ((lane & 3) == 0) {
        if (rL < n) g_asrc[rL] = paL;
        if (rH < n) g_asrc[rH] = paH;
    }

    for (int r = 0; r < 16; r++) {
        int gr = row0 + rbase + r;
        uint2 raw = *(const uint2*)&sA[(rbase + r) * SA_LD + lane * 4];
        float2 f0 = __half22float2(*(__half2*)&raw.x);
        float2 f1 = __half22float2(*(__half2*)&raw.y);
        const float4 wv = *(const float4*)&sW[lane * 4];
        float pd = f0.x * wv.x + f0.y * wv.y + f1.x * wv.z + f1.y * wv.w;
        #pragma unroll
        for (int o = 16; o > 0; o >>= 1) pd += __shfl_xor_sync(0xffffffffu, pd, o);
        if (lane == 0 && gr < n) g_adst[gr] = pd;
    }
}

// K5/K7: fused softmax + CSR aggregation (2 nodes/warp, 16-lane groups).
// cnt from rowstart diffs (deg is re-zeroed by fill for the next replay).
__global__ void aggregate_fused(const float* __restrict__ bias1, int layer, int n) {
    int gw   = (blockIdx.x * blockDim.x + threadIdx.x) >> 5;
    int lane = threadIdx.x & 31;
    int grp  = lane >> 4;
    int gl   = lane & 15;
    int node = gw * 2 + grp;
    if (gw * 2 >= n) return;
    bool active = (node < n);

    int start = 0, cnt = 0;
    float adst = 0.f;
    if (active) {
        start = g_rowstart[node];
        cnt   = g_rowstart[node + 1] - start;
        adst  = g_adst[node];
    }
    int cnt_other = __shfl_xor_sync(0xffffffffu, cnt, 16);
    int cntmax = max(cnt, cnt_other);

    float dsum = 0.f;
    float acc[8];
    #pragma unroll
    for (int q = 0; q < 8; q++) acc[q] = 0.f;

    for (int j0 = 0; j0 < cntmax; j0 += 16) {
        int j = j0 + gl;
        int sN = 0; float w = 0.f;
        if (j < cnt) {
            sN = g_csr[start + j];
            float v = g_asrc[sN] + adst;
            v = (v >= 0.f) ? v : 0.2f * v;
            w = __expf(v);
        }
        dsum += w;
        int m = cntmax - j0; if (m > 16) m = 16;
        int k = 0;
        for (; k + 4 <= m; k += 4) {
            int   si[4]; float wi[4]; uint4 raw[4];
            #pragma unroll
            for (int q = 0; q < 4; q++) {
                si[q] = __shfl_sync(0xffffffffu, sN, k + q, 16);
                wi[q] = __shfl_sync(0xffffffffu, w, k + q, 16);
            }
            #pragma unroll
            for (int q = 0; q < 4; q++)
                raw[q] = *(const uint4*)&g_h16[(size_t)si[q] * NC + gl * 8];
            #pragma unroll
            for (int q = 0; q < 4; q++) {
                float2 f0 = __half22float2(*(__half2*)&raw[q].x);
                float2 f1 = __half22float2(*(__half2*)&raw[q].y);
                float2 f2 = __half22float2(*(__half2*)&raw[q].z);
                float2 f3 = __half22float2(*(__half2*)&raw[q].w);
                acc[0] += wi[q] * f0.x; acc[1] += wi[q] * f0.y;
                acc[2] += wi[q] * f1.x; acc[3] += wi[q] * f1.y;
                acc[4] += wi[q] * f2.x; acc[5] += wi[q] * f2.y;
                acc[6] += wi[q] * f3.x; acc[7] += wi[q] * f3.y;
            }
        }
        for (; k < m; k++) {
            int   sk = __shfl_sync(0xffffffffu, sN, k, 16);
            float wk = __shfl_sync(0xffffffffu, w, k, 16);
            uint4 raw = *(const uint4*)&g_h16[(size_t)sk * NC + gl * 8];
            float2 f0 = __half22float2(*(__half2*)&raw.x);
            float2 f1 = __half22float2(*(__half2*)&raw.y);
            float2 f2 = __half22float2(*(__half2*)&raw.z);
            float2 f3 = __half22float2(*(__half2*)&raw.w);
            acc[0] += wk * f0.x; acc[1] += wk * f0.y;
            acc[2] += wk * f1.x; acc[3] += wk * f1.y;
            acc[4] += wk * f2.x; acc[5] += wk * f2.y;
            acc[6] += wk * f3.x; acc[7] += wk * f3.y;
        }
    }

    #pragma unroll
    for (int o = 8; o > 0; o >>= 1) dsum += __shfl_xor_sync(0xffffffffu, dsum, o);
    float inv = 1.f / (dsum + 1e-16f);
    #pragma unroll
    for (int q = 0; q < 8; q++) acc[q] *= inv;

    if (!active) return;
    if (layer == 0) {
        float4 b0 = *(const float4*)&bias1[gl * 8];
        float4 b1 = *(const float4*)&bias1[gl * 8 + 4];
        union { __half2 h[4]; uint4 u; } cv;
        cv.h[0] = __floats2half2_rn(fmaxf(acc[0] + b0.x, 0.f), fmaxf(acc[1] + b0.y, 0.f));
        cv.h[1] = __floats2half2_rn(fmaxf(acc[2] + b0.z, 0.f), fmaxf(acc[3] + b0.w, 0.f));
        cv.h[2] = __floats2half2_rn(fmaxf(acc[4] + b1.x, 0.f), fmaxf(acc[5] + b1.y, 0.f));
        cv.h[3] = __floats2half2_rn(fmaxf(acc[6] + b1.z, 0.f), fmaxf(acc[7] + b1.w, 0.f));
        *(uint4*)&g_x16[(size_t)node * NC + gl * 8] = cv.u;
    } else {
        *(float4*)&g_agg[(size_t)node * NC + gl * 8] =
            make_float4(acc[0], acc[1], acc[2], acc[3]);
        *(float4*)&g_agg[(size_t)node * NC + gl * 8 + 4] =
            make_float4(acc[4], acc[5], acc[6], acc[7]);
    }
}

// K8: fused mean-pool + head. One block per graph (batch is SORTED).
__global__ void __launch_bounds__(NC) pool_head(
        const float* __restrict__ bias2, const float* __restrict__ Wl,
        const float* __restrict__ bl, float* __restrict__ out, int n) {
    __shared__ __align__(16) float sP[NC];
    __shared__ int sLo, sHi;
    int g = blockIdx.x, c = threadIdx.x;

    if (c == 0) {
        int lo = 0, hi = n;
        while (lo < hi) { int mid = (lo + hi) >> 1; if (g_batch[mid] < g) lo = mid + 1; else hi = mid; }
        sLo = lo;
        lo = 0; hi = n;
        while (lo < hi) { int mid = (lo + hi) >> 1; if (g_batch[mid] < g + 1) lo = mid + 1; else hi = mid; }
        sHi = lo;
    }
    __syncthreads();
    int s = sLo, e = sHi;
    float b = bias2[c];
    float acc = 0.f;
    for (int i = s; i < e; i++)
        acc += fmaxf(g_agg[(size_t)i * NC + c] + b, 0.f);
    float cntf = (float)(e - s);
    sP[c] = acc / fmaxf(cntf, 1.0f);
    __syncthreads();

    float o = bl[c];
    #pragma unroll 4
    for (int k = 0; k < NC; k++) o += sP[k] * Wl[k * NC + c];
    out[g * NC + c] = o;
}

extern "C" void kernel_launch(void* const* d_in, const int* in_sizes, int n_in,
                              void* d_out, int out_size) {
    const float* x     = (const float*)d_in[0];
    const void*  ei    = d_in[1];
    const void*  batch = d_in[2];
    const float* Wsrc1   = (const float*)d_in[3];
    const float* Wdst1   = (const float*)d_in[4];
    const float* attsrc1 = (const float*)d_in[5];
    const float* attdst1 = (const float*)d_in[6];
    const float* bias1   = (const float*)d_in[7];
    const float* Wsrc2   = (const float*)d_in[8];
    const float* Wdst2   = (const float*)d_in[9];
    const float* attsrc2 = (const float*)d_in[10];
    const float* attdst2 = (const float*)d_in[11];
    const float* bias2   = (const float*)d_in[12];
    const float* Wlin    = (const float*)d_in[13];
    const float* blin    = (const float*)d_in[14];

    int n = in_sizes[0] / NC;
    int E = in_sizes[1] / 2;

    int EB          = (E + 255) / 256;
    int gemm_blocks = (n + 127) / 128;
    int agg_blocks  = (n + 15) / 16;
    int scan_blocks = (n + SCAN_CHUNK - 1) / SCAN_CHUNK;
    int scan_total  = scan_blocks * 256;
    int gemm_smem   = 2 * 128 * SA_LD * (int)sizeof(__half);

    static int attr_set = 0;
    if (!attr_set) {
        cudaFuncSetAttribute(hmma_gemm, cudaFuncAttributeMaxDynamicSharedMemorySize,
                             gemm_smem);
        attr_set = 1;
    }

    prep_conv<<<EB + 17, 256>>>(Wsrc1, Wsrc2, Wdst1, attdst1, Wdst2, attdst2,
                                ei, batch, E, n, EB);
    scan_phase1<<<scan_blocks, 256>>>(n);
    scan_phase2<<<1, 1024>>>(scan_total);
    hmma_gemm<<<gemm_blocks, 256, gemm_smem>>>(x, attsrc1, 0, n);  // slot 4: control
    scan_phase3<<<scan_blocks, 256>>>(n);
    fill_kernel<<<EB, 256>>>(E, n);
    aggregate_fused<<<agg_blocks, 256>>>(bias1, 0, n);
    hmma_gemm<<<gemm_blocks, 256, gemm_smem>>>(x, attsrc2, 1, n);
    aggregate_fused<<<agg_blocks, 256>>>(nullptr, 1, n);
    pool_head<<<NG, NC>>>(bias2, Wlin, blin, (float*)d_out, n);
}

// round 17
// speedup vs baseline: 1.0702x; 1.0702x over previous
#include <cuda_runtime.h>
#include <cuda_fp16.h>
#include <math.h>

#define NC 128          // hidden / input dim
#define N_MAX 50000
#define E_MAX 800000
#define NG 64
#define PBLK 592        // scan_fill: 4 blocks/SM x 148 SMs, all resident
#define SA_LD 136       // padded smem stride in halves

// ---- scratch (static device globals; zero-initialized at module load) ----
__device__ __half g_h16[(size_t)N_MAX * NC];   // h (gemm output, gather payload)
__device__ __half g_x16[(size_t)N_MAX * NC];   // layer-2 gemm input (fp16)
__device__ __half g_w16a[NC * NC];             // W_src1 fp16
__device__ __half g_w16b[NC * NC];             // W_src2 fp16
__device__ float g_agg[(size_t)N_MAX * NC];
__device__ float g_asrc[N_MAX];
__device__ float g_adst[N_MAX];
__device__ float g_wdst1[NC];
__device__ float g_wdst2[NC];
__device__ int g_src[E_MAX];
__device__ int g_dst[E_MAX];
__device__ int g_batch[N_MAX];
__device__ int g_is64;
__device__ int g_deg[N_MAX];                   // INVARIANT: zero at kernel_launch entry
__device__ int g_rowstart[N_MAX + 1];          // +1 sentinel
__device__ int g_cursor[N_MAX];
__device__ int g_csr[E_MAX];
__device__ int g_bsum[PBLK];
__device__ unsigned g_bar_cnt;
__device__ unsigned g_bar_rel;

__device__ __forceinline__ void grid_barrier(unsigned nblocks) {
    __threadfence();
    __syncthreads();
    if (threadIdx.x == 0) {
        unsigned my = atomicAdd(&g_bar_cnt, 1u) + 1u;
        unsigned epoch = (my + nblocks - 1u) / nblocks;
        if (my % nblocks == 0u) atomicAdd(&g_bar_rel, 1u);
        while (atomicAdd(&g_bar_rel, 0u) < epoch) __nanosleep(128);
        __threadfence();
    }
    __syncthreads();
}

// K1: W fp16 conv + wdst folds + int64 detect. <<<17,256>>>
__global__ void __launch_bounds__(256) prep_a(
        const float* __restrict__ Ws1, const float* __restrict__ Ws2,
        const float* __restrict__ Wd1, const float* __restrict__ ad1,
        const float* __restrict__ Wd2, const float* __restrict__ ad2,
        const int* __restrict__ ei_words, int E) {
    int tid = threadIdx.x, b = blockIdx.x;

    if (b < 16) {
        int i = b * 256 + tid;           // 4096 float4s total
        const float4* W14 = (const float4*)Ws1;
        const float4* W24 = (const float4*)Ws2;
        float4 v = W14[i];
        union { __half2 h[2]; uint2 u; } cv;
        cv.h[0] = __floats2half2_rn(v.x, v.y);
        cv.h[1] = __floats2half2_rn(v.z, v.w);
        ((uint2*)g_w16a)[i] = cv.u;
        v = W24[i];
        cv.h[0] = __floats2half2_rn(v.x, v.y);
        cv.h[1] = __floats2half2_rn(v.z, v.w);
        ((uint2*)g_w16b)[i] = cv.u;
        return;
    }

    // folds + detect block
    if (tid < NC) {
        float s = 0.f;
        #pragma unroll 4
        for (int c = 0; c < NC; c++) s += Wd1[tid * NC + c] * ad1[c];
        g_wdst1[tid] = s;
    } else {
        int k = tid - NC;
        float s = 0.f;
        #pragma unroll 4
        for (int c = 0; c < NC; c++) s += Wd2[k * NC + c] * ad2[c];
        g_wdst2[k] = s;
    }
    __shared__ int s_or;
    if (tid == 0) s_or = 0;
    __syncthreads();
    int cnt = (E < 2048) ? E : 2048;
    int acc = 0;
    for (int i = tid; i < cnt; i += 256) acc |= ei_words[2 * i + 1];
    atomicOr(&s_or, acc);
    __syncthreads();
    if (tid == 0) g_is64 = (s_or == 0) ? 1 : 0;
}

// K2: convert edges+batch to int32 AND histogram dst degrees (deg zero invariant).
__global__ void conv_hist(const void* __restrict__ ei, const void* __restrict__ batch,
                          int E, int n) {
    int i = blockIdx.x * blockDim.x + threadIdx.x;
    int is64 = g_is64;
    if (i < E) {
        int s, d;
        if (is64) {
            s = (int)((const long long*)ei)[i];
            d = (int)((const long long*)ei)[E + i];
        } else {
            s = ((const int*)ei)[i];
            d = ((const int*)ei)[E + i];
        }
        g_src[i] = s;
        g_dst[i] = d;
        atomicAdd(&g_deg[d], 1);
    }
    if (i < n)
        g_batch[i] = is64 ? (int)((const long long*)batch)[i] : ((const int*)batch)[i];
}

// K3 (persistent, 4 blocks/SM): degree scan, CSR fill, deg re-zero for next replay.
__global__ void __launch_bounds__(256, 4) scan_fill_kernel(int n, int E) {
    __shared__ int sS[256];
    __shared__ int sS2[256];
    int tid = threadIdx.x, b = blockIdx.x;
    int C = (n + PBLK - 1) / PBLK;
    int ept = (C + 255) / 256;
    int nb1 = min(n, (b + 1) * C);
    int t0 = b * C + tid * ept;

    int s = 0;
    for (int i = 0; i < ept; i++) {
        int idx = t0 + i;
        if (idx < nb1) s += g_deg[idx];
    }
    sS[tid] = s;
    __syncthreads();
    for (int off = 1; off < 256; off <<= 1) {
        int v = (tid >= off) ? sS[tid - off] : 0;
        __syncthreads();
        sS[tid] += v;
        __syncthreads();
    }
    int excl = sS[tid] - s;
    if (tid == 255) g_bsum[b] = sS[255];

    grid_barrier(PBLK);

    {
        int part = 0;
        for (int i = tid; i < b; i += 256) part += g_bsum[i];
        sS2[tid] = part;
        __syncthreads();
        for (int off = 128; off > 0; off >>= 1) {
            if (tid < off) sS2[tid] += sS2[tid + off];
            __syncthreads();
        }
    }
    int base = sS2[0] + excl;
    for (int i = 0; i < ept; i++) {
        int idx = t0 + i;
        if (idx < nb1) {
            g_rowstart[idx] = base;
            g_cursor[idx]   = base;
            base += g_deg[idx];
            if (idx == n - 1) g_rowstart[n] = base;   // sentinel
        }
    }

    grid_barrier(PBLK);

    for (int e = b * 256 + tid; e < E; e += PBLK * 256) {
        int slot = atomicAdd(&g_cursor[g_dst[e]], 1);
        g_csr[slot] = g_src[e];
    }
    // re-zero deg for the NEXT launch/replay (deg last read before barrier 2)
    for (int i = b * 256 + tid; i < n; i += PBLK * 256) g_deg[i] = 0;
}

// K4/K6: HMMA node GEMM. CTA = 128 rows x 128 cols x K=128, 8 warps. (R15 verbatim)
__global__ void __launch_bounds__(256) hmma_gemm(const float* __restrict__ x,
                                                 const float* __restrict__ att,
                                                 int layer, int n) {
    extern __shared__ __half smem[];
    __half* sA = smem;                        // 128 x SA_LD
    __half* sB = smem + 128 * SA_LD;          // 128 x SA_LD (W: [k][n])
    __shared__ __align__(16) float sAtt[NC];
    __shared__ __align__(16) float sW[NC];

    int t = threadIdx.x;
    int row0 = blockIdx.x * 128;
    const __half* W16 = (layer == 0) ? g_w16a : g_w16b;
    const float* wdst = (layer == 0) ? g_wdst1 : g_wdst2;
    if (t < NC) sAtt[t] = att[t];
    else        sW[t - NC] = wdst[t - NC];

    const float4* X4 = (const float4*)x;
    #pragma unroll
    for (int i = 0; i < 8; i++) {
        int j = i * 256 + t;
        int r = j >> 4, c8 = j & 15;
        int gr = row0 + r;
        uint4 v = make_uint4(0u, 0u, 0u, 0u);
        if (gr < n) {
            if (layer == 0) {
                float4 v0 = X4[(size_t)gr * 32 + c8 * 2];
                float4 v1 = X4[(size_t)gr * 32 + c8 * 2 + 1];
                union { __half2 h[4]; uint4 u; } cv;
                cv.h[0] = __floats2half2_rn(v0.x, v0.y);
                cv.h[1] = __floats2half2_rn(v0.z, v0.w);
                cv.h[2] = __floats2half2_rn(v1.x, v1.y);
                cv.h[3] = __floats2half2_rn(v1.z, v1.w);
                v = cv.u;
            } else {
                v = *(const uint4*)&g_x16[(size_t)gr * NC + c8 * 8];
            }
        }
        *(uint4*)&sA[r * SA_LD + c8 * 8] = v;
        uint4 wv = *(const uint4*)&W16[r * NC + c8 * 8];
        *(uint4*)&sB[r * SA_LD + c8 * 8] = wv;
    }
    __syncthreads();

    int warp = t >> 5, lane = t & 31;
    int rbase = warp * 16;

    float acc[16][4];
    #pragma unroll
    for (int j = 0; j < 16; j++)
        { acc[j][0] = 0.f; acc[j][1] = 0.f; acc[j][2] = 0.f; acc[j][3] = 0.f; }

    int a_row = rbase + (lane & 7) + ((lane >> 3) & 1) * 8;
    int a_colsel = ((lane >> 4) & 1) * 8;
    int mi = lane >> 3;
    int b_krow = (mi & 1) * 8 + (lane & 7);
    int b_ncol = (mi >> 1) * 8;

    #pragma unroll
    for (int kk = 0; kk < 8; kk++) {
        unsigned a0, a1, a2, a3;
        {
            unsigned aaddr = (unsigned)__cvta_generic_to_shared(
                &sA[a_row * SA_LD + kk * 16 + a_colsel]);
            asm volatile("ldmatrix.sync.aligned.m8n8.x4.shared.b16 {%0,%1,%2,%3}, [%4];"
                         : "=r"(a0), "=r"(a1), "=r"(a2), "=r"(a3) : "r"(aaddr));
        }
        #pragma unroll
        for (int j2 = 0; j2 < 8; j2++) {
            unsigned b0, b1, b2, b3;
            unsigned baddr = (unsigned)__cvta_generic_to_shared(
                &sB[(kk * 16 + b_krow) * SA_LD + j2 * 16 + b_ncol]);
            asm volatile("ldmatrix.sync.aligned.m8n8.x4.trans.shared.b16 {%0,%1,%2,%3}, [%4];"
                         : "=r"(b0), "=r"(b1), "=r"(b2), "=r"(b3) : "r"(baddr));
            int j = j2 * 2;
            asm volatile(
                "mma.sync.aligned.m16n8k16.row.col.f32.f16.f16.f32 "
                "{%0,%1,%2,%3}, {%4,%5,%6,%7}, {%8,%9}, {%0,%1,%2,%3};"
                : "+f"(acc[j][0]), "+f"(acc[j][1]), "+f"(acc[j][2]), "+f"(acc[j][3])
                : "r"(a0), "r"(a1), "r"(a2), "r"(a3), "r"(b0), "r"(b1));
            asm volatile(
                "mma.sync.aligned.m16n8k16.row.col.f32.f16.f16.f32 "
                "{%0,%1,%2,%3}, {%4,%5,%6,%7}, {%8,%9}, {%0,%1,%2,%3};"
                : "+f"(acc[j + 1][0]), "+f"(acc[j + 1][1]), "+f"(acc[j + 1][2]), "+f"(acc[j + 1][3])
                : "r"(a0), "r"(a1), "r"(a2), "r"(a3), "r"(b2), "r"(b3));
        }
    }

    int rL = row0 + rbase + (lane >> 2);
    int rH = rL + 8;
    int colq = (lane & 3) * 2;
    float paL = 0.f, paH = 0.f;
    #pragma unroll
    for (int j = 0; j < 16; j++) {
        float2 av = *(const float2*)&sAtt[j * 8 + colq];
        paL += acc[j][0] * av.x + acc[j][1] * av.y;
        paH += acc[j][2] * av.x + acc[j][3] * av.y;
        if (rL < n)
            *(__half2*)&g_h16[(size_t)rL * NC + j * 8 + colq] =
                __floats2half2_rn(acc[j][0], acc[j][1]);
        if (rH < n)
            *(__half2*)&g_h16[(size_t)rH * NC + j * 8 + colq] =
                __floats2half2_rn(acc[j][2], acc[j][3]);
    }
    paL += __shfl_xor_sync(0xffffffffu, paL, 1);
    paL += __shfl_xor_sync(0xffffffffu, paL, 2);
    paH += __shfl_xor_sync(0xffffffffu, paH, 1);
    paH += __shfl_xor_sync(0xffffffffu, paH, 2);
    if ((lane & 3) == 0) {
        if (rL < n) g_asrc[rL] = paL;
        if (rH < n) g_asrc[rH] = paH;
    }

    for (int r = 0; r < 16; r++) {
        int gr = row0 + rbase + r;
        uint2 raw = *(const uint2*)&sA[(rbase + r) * SA_LD + lane * 4];
        float2 f0 = __half22float2(*(__half2*)&raw.x);
        float2 f1 = __half22float2(*(__half2*)&raw.y);
        const float4 wv = *(const float4*)&sW[lane * 4];
        float pd = f0.x * wv.x + f0.y * wv.y + f1.x * wv.z + f1.y * wv.w;
        #pragma unroll
        for (int o = 16; o > 0; o >>= 1) pd += __shfl_xor_sync(0xffffffffu, pd, o);
        if (lane == 0 && gr < n) g_adst[gr] = pd;
    }
}

// K5/K7: fused softmax + CSR aggregation (2 nodes/warp, 16-lane groups).
// cnt from rowstart diffs.
__global__ void aggregate_fused(const float* __restrict__ bias1, int layer, int n) {
    int gw   = (blockIdx.x * blockDim.x + threadIdx.x) >> 5;
    int lane = threadIdx.x & 31;
    int grp  = lane >> 4;
    int gl   = lane & 15;
    int node = gw * 2 + grp;
    if (gw * 2 >= n) return;
    bool active = (node < n);

    int start = 0, cnt = 0;
    float adst = 0.f;
    if (active) {
        start = g_rowstart[node];
        cnt   = g_rowstart[node + 1] - start;
        adst  = g_adst[node];
    }
    int cnt_other = __shfl_xor_sync(0xffffffffu, cnt, 16);
    int cntmax = max(cnt, cnt_other);

    float dsum = 0.f;
    float acc[8];
    #pragma unroll
    for (int q = 0; q < 8; q++) acc[q] = 0.f;

    for (int j0 = 0; j0 < cntmax; j0 += 16) {
        int j = j0 + gl;
        int sN = 0; float w = 0.f;
        if (j < cnt) {
            sN = g_csr[start + j];
            float v = g_asrc[sN] + adst;
            v = (v >= 0.f) ? v : 0.2f * v;
            w = __expf(v);
        }
        dsum += w;
        int m = cntmax - j0; if (m > 16) m = 16;
        int k = 0;
        for (; k + 4 <= m; k += 4) {
            int   si[4]; float wi[4]; uint4 raw[4];
            #pragma unroll
            for (int q = 0; q < 4; q++) {
                si[q] = __shfl_sync(0xffffffffu, sN, k + q, 16);
                wi[q] = __shfl_sync(0xffffffffu, w, k + q, 16);
            }
            #pragma unroll
            for (int q = 0; q < 4; q++)
                raw[q] = *(const uint4*)&g_h16[(size_t)si[q] * NC + gl * 8];
            #pragma unroll
            for (int q = 0; q < 4; q++) {
                float2 f0 = __half22float2(*(__half2*)&raw[q].x);
                float2 f1 = __half22float2(*(__half2*)&raw[q].y);
                float2 f2 = __half22float2(*(__half2*)&raw[q].z);
                float2 f3 = __half22float2(*(__half2*)&raw[q].w);
                acc[0] += wi[q] * f0.x; acc[1] += wi[q] * f0.y;
                acc[2] += wi[q] * f1.x; acc[3] += wi[q] * f1.y;
                acc[4] += wi[q] * f2.x; acc[5] += wi[q] * f2.y;
                acc[6] += wi[q] * f3.x; acc[7] += wi[q] * f3.y;
            }
        }
        for (; k < m; k++) {
            int   sk = __shfl_sync(0xffffffffu, sN, k, 16);
            float wk = __shfl_sync(0xffffffffu, w, k, 16);
            uint4 raw = *(const uint4*)&g_h16[(size_t)sk * NC + gl * 8];
            float2 f0 = __half22float2(*(__half2*)&raw.x);
            float2 f1 = __half22float2(*(__half2*)&raw.y);
            float2 f2 = __half22float2(*(__half2*)&raw.z);
            float2 f3 = __half22float2(*(__half2*)&raw.w);
            acc[0] += wk * f0.x; acc[1] += wk * f0.y;
            acc[2] += wk * f1.x; acc[3] += wk * f1.y;
            acc[4] += wk * f2.x; acc[5] += wk * f2.y;
            acc[6] += wk * f3.x; acc[7] += wk * f3.y;
        }
    }

    #pragma unroll
    for (int o = 8; o > 0; o >>= 1) dsum += __shfl_xor_sync(0xffffffffu, dsum, o);
    float inv = 1.f / (dsum + 1e-16f);
    #pragma unroll
    for (int q = 0; q < 8; q++) acc[q] *= inv;

    if (!active) return;
    if (layer == 0) {
        float4 b0 = *(const float4*)&bias1[gl * 8];
        float4 b1 = *(const float4*)&bias1[gl * 8 + 4];
        union { __half2 h[4]; uint4 u; } cv;
        cv.h[0] = __floats2half2_rn(fmaxf(acc[0] + b0.x, 0.f), fmaxf(acc[1] + b0.y, 0.f));
        cv.h[1] = __floats2half2_rn(fmaxf(acc[2] + b0.z, 0.f), fmaxf(acc[3] + b0.w, 0.f));
        cv.h[2] = __floats2half2_rn(fmaxf(acc[4] + b1.x, 0.f), fmaxf(acc[5] + b1.y, 0.f));
        cv.h[3] = __floats2half2_rn(fmaxf(acc[6] + b1.z, 0.f), fmaxf(acc[7] + b1.w, 0.f));
        *(uint4*)&g_x16[(size_t)node * NC + gl * 8] = cv.u;
    } else {
        *(float4*)&g_agg[(size_t)node * NC + gl * 8] =
            make_float4(acc[0], acc[1], acc[2], acc[3]);
        *(float4*)&g_agg[(size_t)node * NC + gl * 8 + 4] =
            make_float4(acc[4], acc[5], acc[6], acc[7]);
    }
}

// K8: fused mean-pool + head. One block per graph (batch is SORTED).
__global__ void __launch_bounds__(NC) pool_head(
        const float* __restrict__ bias2, const float* __restrict__ Wl,
        const float* __restrict__ bl, float* __restrict__ out, int n) {
    __shared__ __align__(16) float sP[NC];
    __shared__ int sLo, sHi;
    int g = blockIdx.x, c = threadIdx.x;

    if (c == 0) {
        int lo = 0, hi = n;
        while (lo < hi) { int mid = (lo + hi) >> 1; if (g_batch[mid] < g) lo = mid + 1; else hi = mid; }
        sLo = lo;
        lo = 0; hi = n;
        while (lo < hi) { int mid = (lo + hi) >> 1; if (g_batch[mid] < g + 1) lo = mid + 1; else hi = mid; }
        sHi = lo;
    }
    __syncthreads();
    int s = sLo, e = sHi;
    float b = bias2[c];
    float acc = 0.f;
    for (int i = s; i < e; i++)
        acc += fmaxf(g_agg[(size_t)i * NC + c] + b, 0.f);
    float cntf = (float)(e - s);
    sP[c] = acc / fmaxf(cntf, 1.0f);
    __syncthreads();

    float o = bl[c];
    #pragma unroll 4
    for (int k = 0; k < NC; k++) o += sP[k] * Wl[k * NC + c];
    out[g * NC + c] = o;
}

extern "C" void kernel_launch(void* const* d_in, const int* in_sizes, int n_in,
                              void* d_out, int out_size) {
    const float* x     = (const float*)d_in[0];
    const void*  ei    = d_in[1];
    const void*  batch = d_in[2];
    const float* Wsrc1   = (const float*)d_in[3];
    const float* Wdst1   = (const float*)d_in[4];
    const float* attsrc1 = (const float*)d_in[5];
    const float* attdst1 = (const float*)d_in[6];
    const float* bias1   = (const float*)d_in[7];
    const float* Wsrc2   = (const float*)d_in[8];
    const float* Wdst2   = (const float*)d_in[9];
    const float* attsrc2 = (const float*)d_in[10];
    const float* attdst2 = (const float*)d_in[11];
    const float* bias2   = (const float*)d_in[12];
    const float* Wlin    = (const float*)d_in[13];
    const float* blin    = (const float*)d_in[14];

    int n = in_sizes[0] / NC;
    int E = in_sizes[1] / 2;

    int gemm_blocks = (n + 127) / 128;
    int agg_blocks  = (n + 15) / 16;
    int e_blocks    = (E + 255) / 256;
    int gemm_smem   = 2 * 128 * SA_LD * (int)sizeof(__half);

    // One-time setup happens on the FIRST (uncaptured correctness) call.
    static cudaStream_t s_side = nullptr;
    static cudaEvent_t ev_fork = nullptr, ev_join = nullptr;
    if (s_side == nullptr) {
        cudaFuncSetAttribute(hmma_gemm, cudaFuncAttributeMaxDynamicSharedMemorySize,
                             gemm_smem);
        cudaStreamCreateWithFlags(&s_side, cudaStreamNonBlocking);
        cudaEventCreateWithFlags(&ev_fork, cudaEventDisableTiming);
        cudaEventCreateWithFlags(&ev_join, cudaEventDisableTiming);
    }

    // prep (weights + detect) — both branches depend on it
    prep_a<<<17, 256>>>(Wsrc1, Wsrc2, Wdst1, attdst1, Wdst2, attdst2,
                        (const int*)ei, E);

    // fork: gemm0 on side stream, CSR chain on main stream (independent)
    cudaEventRecord(ev_fork, 0);
    cudaStreamWaitEvent(s_side, ev_fork, 0);
    hmma_gemm<<<gemm_blocks, 256, gemm_smem, s_side>>>(x, attsrc1, 0, n);
    cudaEventRecord(ev_join, s_side);

    conv_hist<<<e_blocks, 256>>>(ei, batch, E, n);
    scan_fill_kernel<<<PBLK, 256>>>(n, E);

    // join
    cudaStreamWaitEvent(0, ev_join, 0);

    aggregate_fused<<<agg_blocks, 256>>>(bias1, 0, n);
    hmma_gemm<<<gemm_blocks, 256, gemm_smem>>>(x, attsrc2, 1, n);
    aggregate_fused<<<agg_blocks, 256>>>(nullptr, 1, n);
    pool_head<<<NG, NC>>>(bias2, Wlin, blin, (float*)d_out, n);
}